// round 10
// baseline (speedup 1.0000x reference)
#include <cuda_runtime.h>
#include <math.h>

#define KK 16
#define TT 40
#define BB 16
#define NN 32
#define BN 512
#define KBN 8192
#define HH2 80
#define C1 16
#define C2 32
#define NBIN 36
#define HWSZ (BB*NN*NBIN*48)     // 884736 per step

typedef unsigned long long ull;

__device__ float g_conv1[BB*C1*HH2*HH2];
__device__ float g_fmap [BB*HH2*HH2*C2];
__device__ float g_lhalf[KK*TT*BN*48];
__device__ int   g_cnt[KK*TT*BN];
__device__ float2 g_ent[(size_t)KK*TT*BN*32];
__device__ float g_WscfT[1728*48];               // scfw transposed
__device__ float g_HWhist[(size_t)TT*HWSZ];      // 141.6 MB
__device__ float g_h0full[(TT+1)*BN*48];         // k=0 hidden history
__device__ float g_hfin[KBN*48];
__device__ float g_score[KBN];

// ---- f32x2 / fast-math helpers ----
__device__ __forceinline__ ull pk2(float lo, float hi) {
    ull r; asm("mov.b64 %0, {%1,%2};" : "=l"(r) : "f"(lo), "f"(hi)); return r;
}
__device__ __forceinline__ void upk2(ull v, float& lo, float& hi) {
    asm("mov.b64 {%0,%1}, %2;" : "=f"(lo), "=f"(hi) : "l"(v));
}
__device__ __forceinline__ void fma2(ull& a, ull x, ull y) {
    asm("fma.rn.f32x2 %0, %1, %2, %0;" : "+l"(a) : "l"(x), "l"(y));
}
__device__ __forceinline__ float sigf(float x) {
    float e; asm("ex2.approx.f32 %0, %1;" : "=f"(e) : "f"(x * -1.4426950408889634f));
    float r; asm("rcp.approx.f32 %0, %1;" : "=f"(r) : "f"(1.f + e));
    return r;
}
__device__ __forceinline__ float tanh_fast(float x) { return 2.f*sigf(2.f*x) - 1.f; }

// ---------------- conv1 ----------------
__global__ void conv1_kernel(const float* __restrict__ img,
                             const float* __restrict__ w,
                             const float* __restrict__ bias) {
    __shared__ float sW[1600];
    __shared__ float sB[16];
    for (int i = threadIdx.x; i < 1600; i += 256) sW[i] = w[i];
    if (threadIdx.x < 16) sB[threadIdx.x] = bias[threadIdx.x];
    __syncthreads();
    int idx = blockIdx.x*256 + threadIdx.x;
    int x = idx % HH2; int y = (idx/HH2) % HH2;
    int oc = (idx/(HH2*HH2)) % C1; int b = idx/(HH2*HH2*C1);
    float acc = sB[oc];
    for (int ic = 0; ic < 4; ic++)
        for (int ky = 0; ky < 5; ky++) {
            int iy = 2*y - 2 + ky;
            if (iy < 0 || iy >= 160) continue;
            const float* ip = img + ((b*4+ic)*160 + iy)*160;
            const float* wp = sW + (oc*4+ic)*25 + ky*5;
            #pragma unroll
            for (int kx = 0; kx < 5; kx++) {
                int ix = 2*x - 2 + kx;
                if (ix < 0 || ix >= 160) continue;
                acc += ip[ix] * wp[kx];
            }
        }
    g_conv1[idx] = fmaxf(acc, 0.f);
}

// ---------------- conv2 ----------------
__global__ void conv2_kernel(const float* __restrict__ w2,
                             const float* __restrict__ b2) {
    __shared__ float sIn[6400];
    __shared__ __align__(16) float sW[3200];
    int blk = blockIdx.x;                       // 1600
    int ocg = blk % 4; int tile = (blk/4) % 25; int b = blk/100;
    int ty0 = (tile/5)*16, tx0 = (tile%5)*16;
    int tid = threadIdx.x;                      // 128
    for (int i = tid; i < 6400; i += 128) {
        int ic = i/400; int rem = i%400; int ly = rem/20, lx = rem%20;
        int iy = ty0 + ly - 2, ix = tx0 + lx - 2;
        sIn[i] = (iy>=0 && iy<HH2 && ix>=0 && ix<HH2)
                 ? g_conv1[((b*C1+ic)*HH2+iy)*HH2+ix] : 0.f;
    }
    for (int i = tid; i < 3200; i += 128) {
        int ic = i/200, rem = i%200, k2 = rem/8, ocl = rem%8;
        sW[i] = w2[(ocg*8+ocl)*400 + ic*25 + k2];
    }
    __syncthreads();
    int tx = tid % 16, tyh = tid / 16;
    ull a0[4], a1[4];
    #pragma unroll
    for (int o2 = 0; o2 < 4; o2++) {
        a0[o2] = pk2(b2[ocg*8+2*o2], b2[ocg*8+2*o2+1]);
        a1[o2] = a0[o2];
    }
    for (int ic = 0; ic < 16; ic++) {
        float in0[25], in1[25];
        const float* p0 = sIn + ic*400 + tyh*20 + tx;
        const float* p1 = p0 + 160;
        #pragma unroll
        for (int ky = 0; ky < 5; ky++)
            #pragma unroll
            for (int kx = 0; kx < 5; kx++) {
                in0[ky*5+kx] = p0[ky*20+kx];
                in1[ky*5+kx] = p1[ky*20+kx];
            }
        #pragma unroll
        for (int k2 = 0; k2 < 25; k2++) {
            ull i0 = pk2(in0[k2], in0[k2]);
            ull i1 = pk2(in1[k2], in1[k2]);
            const float* wb = &sW[(ic*25+k2)*8];
            #pragma unroll
            for (int o2 = 0; o2 < 4; o2++) {
                ull w = *(const ull*)(wb + 2*o2);
                fma2(a0[o2], i0, w); fma2(a1[o2], i1, w);
            }
        }
    }
    #pragma unroll
    for (int o2 = 0; o2 < 4; o2++) {
        float v0, v1, u0, u1;
        upk2(a0[o2], v0, v1); upk2(a1[o2], u0, u1);
        int oc = ocg*8 + 2*o2;
        float* d0 = &g_fmap[((b*HH2 + ty0+tyh  )*HH2 + tx0+tx)*C2 + oc];
        float* d1 = &g_fmap[((b*HH2 + ty0+tyh+8)*HH2 + tx0+tx)*C2 + oc];
        d0[0] = fmaxf(v0, 0.f); d0[1] = fmaxf(v1, 0.f);
        d1[0] = fmaxf(u0, 0.f); d1[1] = fmaxf(u1, 0.f);
    }
}

// ---------------- transpose fc_scf_w ----------------
__global__ void transposeW_kernel(const float* __restrict__ w) {
    int idx = blockIdx.x*256 + threadIdx.x;    // 82944
    int c = idx / 1728; int oh = idx % 1728;
    g_WscfT[oh*48 + c] = w[idx];
}

// ---------------- lhalf ----------------
__global__ void lhalf_kernel(const float* __restrict__ y_path,
                             const float* __restrict__ cur_loc,
                             const float* __restrict__ fvw,
                             const float* __restrict__ fvb) {
    int idx = blockIdx.x*256 + threadIdx.x;    // 7,864,320
    int cp = idx % 24; int row = idx / 24;
    int kt = row / BN, i2 = row % BN;
    int t = kt % TT; int b = i2 >> 5;
    float px = y_path[row*2], py = y_path[row*2+1];
    float2 out;
    if (cp < 16) {
        int u = 40 - (int)py; u = min(max(u,0), HH2-1);
        int v = (int)px;      v = min(max(v,0), HH2-1);
        out = *(const float2*)&g_fmap[((b*HH2+u)*HH2+v)*C2 + 2*cp];
    } else {
        int cc = 2*cp - 32;
        float pvx, pvy;
        if (t == 0) { pvx = cur_loc[i2*2]; pvy = cur_loc[i2*2+1]; }
        else { pvx = y_path[(row-BN)*2]; pvy = y_path[(row-BN)*2+1]; }
        float vx = (px-pvx)*10.f, vy = (py-pvy)*10.f;
        out.x = fvb[cc]   + vx*fvw[cc*2]   + vy*fvw[cc*2+1];
        out.y = fvb[cc+1] + vx*fvw[cc*2+2] + vy*fvw[cc*2+3];
    }
    *(float2*)&g_lhalf[(size_t)idx*2] = out;
}

// ---------------- bins ----------------
__device__ __forceinline__ int bin_of(float dx, float dy) {
    float dist = sqrtf(dx*dx + dy*dy);
    float dc = dist < 1e-10f ? 1e-10f : dist;
    float ct = acosf(fminf(fmaxf(dx/dc, -1.f), 1.f));
    float theta = (dy < -0.01f) ? (6.2831853071795864f - ct) : ct;
    const float R_STEP  = (float)(3.5/6.0);
    const float TH_STEP = (float)(6.283185307179586/6.0);
    int ub = (int)((dist - 0.5f)/R_STEP); ub = min(max(ub,0),5);
    int vb = (int)(theta/TH_STEP);        vb = min(max(vb,0),5);
    return ub*6 + vb;
}

__global__ void bins_kernel(const float* __restrict__ y_path) {
    __shared__ float sP[4][NN][2];
    int tid = threadIdx.x;
    int g = tid >> 5, j = tid & 31;
    int grp = blockIdx.x*4 + g;                // 10240
    int b = grp % BB; int kt = grp / BB;
    int rowbase = kt*BN + b*NN;
    sP[g][j][0] = y_path[(rowbase+j)*2];
    sP[g][j][1] = y_path[(rowbase+j)*2+1];
    __syncwarp();
    float pjx = sP[g][j][0], pjy = sP[g][j][1];
    unsigned maskbits = 0;
    #pragma unroll
    for (int n2 = 0; n2 < NN; n2++) {
        float dx = sP[g][n2][0] - pjx;
        float dy = sP[g][n2][1] - pjy;
        float dist = sqrtf(dx*dx + dy*dy);
        if (n2 != j && dist >= 0.5f && dist <= 4.0f) maskbits |= 1u << n2;
    }
    size_t rowid = rowbase + j;
    int e = 0;
    unsigned m1 = maskbits;
    while (m1) {
        int n2 = __ffs(m1) - 1; m1 &= m1 - 1;
        int bn = bin_of(sP[g][n2][0]-pjx, sP[g][n2][1]-pjy);
        int cnt = 0;
        unsigned mq = maskbits;
        while (mq) {
            int q = __ffs(mq) - 1; mq &= mq - 1;
            cnt += (bin_of(sP[g][q][0]-pjx, sP[g][q][1]-pjy) == bn);
        }
        g_ent[rowid*32 + e] = make_float2(1.f/(float)cnt,
                            __int_as_float((n2*NBIN + bn)*48));
        e++;
    }
    g_cnt[rowid] = e;
}

// ---------------- init: h0 history slot 0 ----------------
__global__ void init_kernel(const float* __restrict__ hx) {
    int idx = blockIdx.x*256 + threadIdx.x;    // 24576
    g_h0full[idx] = hx[idx];
}

// ---------------- scanA: 16 independent per-batch k=0 chains ----------------
__global__ void __launch_bounds__(512, 1) scanA_kernel(
        const float* __restrict__ hx,   const float* __restrict__ whh,
        const float* __restrict__ bhh,  const float* __restrict__ wih,
        const float* __restrict__ bih,  const float* __restrict__ scfb,
        const float* __restrict__ scw) {
    extern __shared__ float sm[];
    float* sWih = sm;              // 13920 (96 x 145)
    float* sWhh = sm + 13920;      // 6960  (48 x 145)
    float* sBi  = sm + 20880;      // 144
    float* sBh  = sm + 21024;      // 144
    float* sFb  = sm + 21168;      // 48
    float* sScw = sm + 21216;      // 48
    float* sXT  = sm + 21264;      // 3264 (96 x 34): x^T [m][row]
    float* sHT2 = sm + 24528;      // 1632 (48 x 34): h^T
    float* sGT  = sm + 26160;      // 4896 (144 x 34)
    float* sGnT = sm + 31056;      // 1632 (48 x 34)
    float2* sEnt = (float2*)(sm + 32688);  // 32 x 32 float2 = 2048 fl
    int*   sCnt = (int*)(sm + 34736);      // 32
    float* sScA = sm + 34768;      // 32   -> total 34800 fl = 139200 B

    int tid = threadIdx.x;
    int b = blockIdx.x;            // 16 blocks, one batch each
    int r0p = b * 32;

    for (int i = tid; i < 13824; i += 512) {
        int c = i / 96, m = i % 96;
        sWih[m*145 + c] = wih[i];
    }
    for (int i = tid; i < 6912; i += 512) {
        int c = i / 48, m = i % 48;
        sWhh[m*145 + c] = whh[i];
    }
    if (tid < 144) { sBi[tid] = bih[tid]; sBh[tid] = bhh[tid]; }
    if (tid < 48)  { sFb[tid] = scfb[tid]; sScw[tid] = scw[tid]; }
    if (tid < 32)  sScA[tid] = 0.f;
    for (int i = tid; i < 1536; i += 512) {
        int row = i / 48, c = i % 48;
        sHT2[c*34 + row] = hx[r0p*48 + i];
    }
    __syncthreads();

    for (int t = 0; t < TT; t++) {
        // load lhalf (k=0 slice) transposed + entries
        for (int i = tid; i < 1536; i += 512) {
            int row = i / 48, c = i % 48;
            sXT[c*34 + row] = g_lhalf[(size_t)(t*BN + r0p)*48 + i];
        }
        if (tid < 32) {
            int cnt = g_cnt[t*BN + r0p + tid];
            sCnt[tid] = cnt;
            for (int e = 0; e < cnt; e++)
                sEnt[tid*32 + e] = g_ent[(size_t)(t*BN + r0p + tid)*32 + e];
        }
        __syncthreads();
        // rhalf: direct per-entry dot against WscfT (coalesced c)
        for (int out = tid; out < 1536; out += 512) {
            int row = out / 48, c = out % 48;
            float acc = sFb[c];
            int cnt = sCnt[row];
            for (int e = 0; e < cnt; e++) {
                float2 en = sEnt[row*32 + e];
                int off = __float_as_int(en.y);          // (n2*36+bin)*48
                int n2  = off / (NBIN*48);
                int rem = off - n2*NBIN*48;              // bin*48
                const float* wt = g_WscfT + (size_t)rem*48 + c;
                float s = 0.f;
                #pragma unroll
                for (int h = 0; h < 48; h++)
                    s += sHT2[h*34 + n2] * wt[h*48];
                acc += en.x * s;
            }
            sXT[(48+c)*34 + row] = acc;
        }
        __syncthreads();
        // GEMM: items (c 0..191) x (rowg 0..7), 4-row f32x2 tiles
        for (int it = tid; it < 1536; it += 512) {
            int c = it % 192, rowg = it / 192, rl = rowg*4;
            if (c < 144) {
                int gate = c / 48;
                float base = sBi[c] + (gate < 2 ? sBh[c] : 0.f);
                ull a0 = pk2(base, base), a1 = a0;
                for (int m = 0; m < 96; m++) {
                    ull w = pk2(sWih[m*145+c], sWih[m*145+c]);
                    fma2(a0, *(const ull*)&sXT[m*34 + rl],     w);
                    fma2(a1, *(const ull*)&sXT[m*34 + rl + 2], w);
                }
                if (gate < 2) {
                    for (int m = 0; m < 48; m++) {
                        ull w = pk2(sWhh[m*145+c], sWhh[m*145+c]);
                        fma2(a0, *(const ull*)&sHT2[m*34 + rl],     w);
                        fma2(a1, *(const ull*)&sHT2[m*34 + rl + 2], w);
                    }
                }
                float v0, v1, v2, v3;
                upk2(a0, v0, v1); upk2(a1, v2, v3);
                sGT[c*34 + rl]   = v0; sGT[c*34 + rl+1] = v1;
                sGT[c*34 + rl+2] = v2; sGT[c*34 + rl+3] = v3;
            } else {
                int cc = c - 144;
                float base = sBh[96+cc];
                ull a0 = pk2(base, base), a1 = a0;
                for (int m = 0; m < 48; m++) {
                    ull w = pk2(sWhh[m*145+96+cc], sWhh[m*145+96+cc]);
                    fma2(a0, *(const ull*)&sHT2[m*34 + rl],     w);
                    fma2(a1, *(const ull*)&sHT2[m*34 + rl + 2], w);
                }
                float v0, v1, v2, v3;
                upk2(a0, v0, v1); upk2(a1, v2, v3);
                sGnT[cc*34 + rl]   = v0; sGnT[cc*34 + rl+1] = v1;
                sGnT[cc*34 + rl+2] = v2; sGnT[cc*34 + rl+3] = v3;
            }
        }
        __syncthreads();
        // GRU + publish h0 history
        float* dst = g_h0full + (size_t)(t+1)*(BN*48) + r0p*48;
        for (int i = tid; i < 1536; i += 512) {
            int row = i / 48, cc = i % 48;
            float r = sigf(sGT[cc*34 + row]);
            float z = sigf(sGT[(48+cc)*34 + row]);
            float n = tanh_fast(sGT[(96+cc)*34 + row] + r*sGnT[cc*34 + row]);
            float hv = (1.f - z)*n + z*sHT2[cc*34 + row];
            sHT2[cc*34 + row] = hv;
            dst[i] = hv;
        }
        __syncthreads();
        if (tid < 32) {
            float s = 0.f;
            #pragma unroll
            for (int c = 0; c < 48; c++) s += sHT2[c*34 + tid] * sScw[c];
            sScA[tid] += s;
        }
        __syncthreads();
    }
    for (int i = tid; i < 1536; i += 512) {
        int row = i / 48, c = i % 48;
        g_hfin[(size_t)r0p*48 + i] = sHT2[c*34 + row];
    }
    if (tid < 32) g_score[r0p + tid] = sScA[tid];
}

// ---------------- scanB: HW history, fully parallel over (t,b,og) ----------
__global__ void __launch_bounds__(256) scanB_kernel() {
    __shared__ float sWT[9216];
    __shared__ float sHnT[1584];
    int tid = threadIdx.x, blk = blockIdx.x;   // 5760 = 40*144
    int t = blk / 144, sub = blk % 144;
    int bA = sub / 9, og = sub % 9;
    for (int i = tid; i < 9216; i += 256) sWT[i] = g_WscfT[og*9216 + i];
    const float* hs = g_h0full + (size_t)t*(BN*48) + bA*1536;
    for (int i = tid; i < 1536; i += 256) {
        int n2 = i / 48, hh = i % 48;
        sHnT[hh*33 + n2] = hs[i];
    }
    __syncthreads();
    float* hist = g_HWhist + (size_t)t*HWSZ;
    for (int it = tid; it < 768; it += 256) {
        int cg = it % 24, oo = (it/24) & 3, n2g = it / 96;
        float a0[4], a1[4];
        #pragma unroll
        for (int i = 0; i < 4; i++) { a0[i] = 0.f; a1[i] = 0.f; }
        const float* wt = sWT + oo*2304;
        for (int hh = 0; hh < 48; hh++) {
            float w0 = wt[hh*48 + cg], w1 = wt[hh*48 + cg + 24];
            #pragma unroll
            for (int i = 0; i < 4; i++) {
                float hv = sHnT[hh*33 + n2g*4 + i];
                a0[i] += hv*w0; a1[i] += hv*w1;
            }
        }
        #pragma unroll
        for (int i = 0; i < 4; i++) {
            int base = ((bA*NN + n2g*4+i)*NBIN + og*4 + oo)*48;
            hist[base + cg]      = a0[i];
            hist[base + cg + 24] = a1[i];
        }
    }
}

// ---------------- scanC: k=1..15, barrier-free ----------------
__global__ void __launch_bounds__(512, 1) scanC_kernel(
        const float* __restrict__ hx,   const float* __restrict__ whh,
        const float* __restrict__ bhh,  const float* __restrict__ wih,
        const float* __restrict__ bih,  const float* __restrict__ scfb,
        const float* __restrict__ scw) {
    extern __shared__ float sm[];
    float* sWih = sm;              // 13920
    float* sWhh = sm + 13920;      // 6960
    float* sBi  = sm + 20880;      // 144
    float* sBh  = sm + 21024;      // 144
    float* sFb  = sm + 21168;      // 48
    float* sScw = sm + 21216;      // 48
    float* sLT  = sm + 21264;      // 3168 (48 x 66)
    float* sRT  = sm + 24432;      // 3168
    float* sHT  = sm + 27600;      // 3168
    float* sNT  = sm + 30768;      // 3168
    float2* sEnt = (float2*)(sm + 33936);  // 2048 float2
    int*   sCnt = (int*)(sm + 38032);      // 64
    float* sSc  = sm + 38096;      // 1536
    float* sScA = sm + 39632;      // 64 -> total 39696 fl

    int tid = threadIdx.x, blk = blockIdx.x;   // 120 blocks
    int r0 = 512 + blk*64;
    int kq = r0 >> 9, i2b = r0 & 511;

    for (int i = tid; i < 13824; i += 512) {
        int c = i / 96, m = i % 96;
        sWih[m*145 + c] = wih[i];
    }
    for (int i = tid; i < 6912; i += 512) {
        int c = i / 48, m = i % 48;
        sWhh[m*145 + c] = whh[i];
    }
    if (tid < 144) { sBi[tid] = bih[tid]; sBh[tid] = bhh[tid]; }
    if (tid < 48)  { sFb[tid] = scfb[tid]; sScw[tid] = scw[tid]; }
    if (tid < 64)  sScA[tid] = 0.f;
    for (int i = tid; i < 3072; i += 512) {
        int row = i / 48, c = i % 48;
        sHT[c*66 + row] = hx[(i2b + row)*48 + c];
    }
    __syncthreads();

    for (int t = 0; t < TT; t++) {
        int gb = (kq*TT + t)*BN + i2b;
        for (int i = tid; i < 3072; i += 512) {
            int row = i / 48, c = i % 48;
            sLT[c*66 + row] = g_lhalf[(size_t)gb*48 + i];
        }
        if (tid < 64) {
            int cnt = g_cnt[gb + tid];
            sCnt[tid] = cnt;
            for (int e = 0; e < cnt; e++)
                sEnt[tid*32 + e] = g_ent[(size_t)(gb + tid)*32 + e];
        }
        __syncthreads();
        const float* hist = g_HWhist + (size_t)t*HWSZ;
        for (int out = tid; out < 3072; out += 512) {
            int lr = out / 48, c = out % 48;
            int cnt = sCnt[lr];
            float acc = sFb[c];
            const float* hwb = hist + ((i2b + lr) >> 5)*(NN*NBIN*48);
            for (int e = 0; e < cnt; e++) {
                float2 en = sEnt[lr*32 + e];
                acc += en.x * __ldg(hwb + __float_as_int(en.y) + c);
            }
            sRT[c*66 + lr] = acc;
        }
        __syncthreads();
        if (tid < 384) {
            int cg = tid % 24, rg = tid / 24, rl = rg*4;
            ull gr2[2][2], gz2[2][2], gnx2[2][2], gnh2[2][2];
            #pragma unroll
            for (int jj = 0; jj < 2; jj++) {
                int c = cg + 24*jj;
                ull t0;
                t0 = pk2(sBi[c]+sBh[c],       sBi[c]+sBh[c]);
                gr2[0][jj] = t0; gr2[1][jj] = t0;
                t0 = pk2(sBi[48+c]+sBh[48+c], sBi[48+c]+sBh[48+c]);
                gz2[0][jj] = t0; gz2[1][jj] = t0;
                t0 = pk2(sBi[96+c], sBi[96+c]);
                gnx2[0][jj] = t0; gnx2[1][jj] = t0;
                t0 = pk2(sBh[96+c], sBh[96+c]);
                gnh2[0][jj] = t0; gnh2[1][jj] = t0;
            }
            #define SEG(XS, WP, NACC)                                          \
            for (int m = 0; m < 48; m++) {                                     \
                ull x0 = *(const ull*)&XS[m*66 + rl];                          \
                ull x1 = *(const ull*)&XS[m*66 + rl + 2];                      \
                const float* wp = WP + m*145;                                  \
                _Pragma("unroll")                                              \
                for (int jj = 0; jj < 2; jj++) {                               \
                    int c = cg + 24*jj;                                        \
                    ull wr = pk2(wp[c], wp[c]);                                \
                    ull wz = pk2(wp[48+c], wp[48+c]);                          \
                    ull wn = pk2(wp[96+c], wp[96+c]);                          \
                    fma2(gr2[0][jj], x0, wr); fma2(gr2[1][jj], x1, wr);        \
                    fma2(gz2[0][jj], x0, wz); fma2(gz2[1][jj], x1, wz);        \
                    fma2(NACC[0][jj], x0, wn); fma2(NACC[1][jj], x1, wn);      \
                }                                                              \
            }
            SEG(sLT, sWih, gnx2)
            SEG((sRT), (sWih + 48*145), gnx2)
            SEG(sHT, sWhh, gnh2)
            #undef SEG
            float scacc[4] = {0.f, 0.f, 0.f, 0.f};
            #pragma unroll
            for (int p = 0; p < 2; p++) {
                #pragma unroll
                for (int jj = 0; jj < 2; jj++) {
                    int c = cg + 24*jj;
                    float grl, grh, gzl, gzh, gxl, gxh, ghl, ghh;
                    upk2(gr2[p][jj],  grl, grh);
                    upk2(gz2[p][jj],  gzl, gzh);
                    upk2(gnx2[p][jj], gxl, gxh);
                    upk2(gnh2[p][jj], ghl, ghh);
                    int rowl = rl + 2*p, rowh = rowl + 1;
                    float r0f = sigf(grl), z0f = sigf(gzl);
                    float n0f = tanh_fast(gxl + r0f*ghl);
                    float h0f = (1.f - z0f)*n0f + z0f*sHT[c*66 + rowl];
                    sNT[c*66 + rowl] = h0f;
                    scacc[2*p]   += h0f * sScw[c];
                    float r1f = sigf(grh), z1f = sigf(gzh);
                    float n1f = tanh_fast(gxh + r1f*ghh);
                    float h1f = (1.f - z1f)*n1f + z1f*sHT[c*66 + rowh];
                    sNT[c*66 + rowh] = h1f;
                    scacc[2*p+1] += h1f * sScw[c];
                }
            }
            #pragma unroll
            for (int i = 0; i < 4; i++) sSc[(rl+i)*24 + cg] = scacc[i];
        }
        __syncthreads();
        for (int i = tid; i < 3168; i += 512) sHT[i] = sNT[i];
        if (tid < 64) {
            float s = 0.f;
            #pragma unroll
            for (int c = 0; c < 24; c++) s += sSc[tid*24 + c];
            sScA[tid] += s;
        }
        __syncthreads();
    }
    for (int i = tid; i < 3072; i += 512) {
        int row = i / 48, c = i % 48;
        g_hfin[(size_t)r0*48 + i] = sHT[c*66 + row];
    }
    if (tid < 64) g_score[r0 + tid] = sScA[tid];
}

// ---------------- final ----------------
__global__ void final_kernel(const float* __restrict__ dyw,
                             const float* __restrict__ dyb,
                             const float* __restrict__ scb,
                             float* __restrict__ out) {
    int idx = blockIdx.x*256 + threadIdx.x;    // 663552
    if (idx < KBN*80) {
        int row = idx / 80, c = idx % 80;
        float acc = dyb[c];
        const float* hr = g_hfin + row*48;
        const float* w  = dyw + c*48;
        #pragma unroll 8
        for (int hh = 0; hh < 48; hh++) acc += hr[hh]*w[hh];
        int k = row >> 9, i2 = row & 511;
        int d = c / 40, tt = c % 40;
        out[((k*TT + tt)*BN + i2)*2 + d] = acc;
    } else {
        int row = idx - KBN*80;
        out[KBN*80 + row] = g_score[row] + 40.f*scb[0];
    }
}

// ---------------- launcher ----------------
extern "C" void kernel_launch(void* const* d_in, const int* in_sizes, int n_in,
                              void* d_out, int out_size) {
    const float* hx      = (const float*)d_in[0];
    const float* cur_loc = (const float*)d_in[1];
    const float* y_path  = (const float*)d_in[2];
    const float* image   = (const float*)d_in[3];
    const float* c1w     = (const float*)d_in[4];
    const float* c1b     = (const float*)d_in[5];
    const float* c2w     = (const float*)d_in[6];
    const float* c2b     = (const float*)d_in[7];
    const float* fvw     = (const float*)d_in[8];
    const float* fvb     = (const float*)d_in[9];
    const float* scfw    = (const float*)d_in[10];
    const float* scfb    = (const float*)d_in[11];
    const float* wih     = (const float*)d_in[12];
    const float* whh     = (const float*)d_in[13];
    const float* bih     = (const float*)d_in[14];
    const float* bhh     = (const float*)d_in[15];
    const float* dyw     = (const float*)d_in[16];
    const float* dyb     = (const float*)d_in[17];
    const float* scw     = (const float*)d_in[18];
    const float* scb     = (const float*)d_in[19];

    const int SMA = 34800 * 4;     // 139200 B
    const int SMC = 39696 * 4;     // 158784 B
    cudaFuncSetAttribute(scanA_kernel,
                         cudaFuncAttributeMaxDynamicSharedMemorySize, SMA);
    cudaFuncSetAttribute(scanC_kernel,
                         cudaFuncAttributeMaxDynamicSharedMemorySize, SMC);

    conv1_kernel<<<6400, 256>>>(image, c1w, c1b);
    conv2_kernel<<<1600, 128>>>(c2w, c2b);
    lhalf_kernel<<<30720,256>>>(y_path, cur_loc, fvw, fvb);
    transposeW_kernel<<<324, 256>>>(scfw);
    bins_kernel <<<2560, 128>>>(y_path);
    init_kernel <<<96,   256>>>(hx);
    scanA_kernel<<<16,   512, SMA>>>(hx, whh, bhh, wih, bih, scfb, scw);
    scanB_kernel<<<5760, 256>>>();
    scanC_kernel<<<120,  512, SMC>>>(hx, whh, bhh, wih, bih, scfb, scw);
    final_kernel<<<2592, 256>>>(dyw, dyb, scb, (float*)d_out);
}

// round 11
// speedup vs baseline: 1.3881x; 1.3881x over previous
#include <cuda_runtime.h>
#include <math.h>

#define KK 16
#define TT 40
#define BB 16
#define NN 32
#define BN 512
#define KBN 8192
#define HH2 80
#define C1 16
#define C2 32
#define NBIN 36
#define NBLK 144
#define TSC 512

typedef unsigned long long ull;

__device__ float g_conv1[BB*C1*HH2*HH2];
__device__ float g_fmap [BB*HH2*HH2*C2];
__device__ float g_lhalf[KK*TT*BN*48];
__device__ int   g_cnt[KK*TT*BN];
__device__ float2 g_ent[(size_t)KK*TT*BN*32];
__device__ float g_HW [BB*NN*NBIN*48];
__device__ float g_h0 [2][BN*48];
__device__ float g_hfin[KBN*48];
__device__ float g_score[KBN];
__device__ unsigned g_bar_count;
__device__ unsigned g_bar_flag;

// ---- f32x2 / fast-math helpers ----
__device__ __forceinline__ ull pk2(float lo, float hi) {
    ull r; asm("mov.b64 %0, {%1,%2};" : "=l"(r) : "f"(lo), "f"(hi)); return r;
}
__device__ __forceinline__ void upk2(ull v, float& lo, float& hi) {
    asm("mov.b64 {%0,%1}, %2;" : "=f"(lo), "=f"(hi) : "l"(v));
}
__device__ __forceinline__ void fma2(ull& a, ull x, ull y) {
    asm("fma.rn.f32x2 %0, %1, %2, %0;" : "+l"(a) : "l"(x), "l"(y));
}
__device__ __forceinline__ float sigf(float x) {
    float e; asm("ex2.approx.f32 %0, %1;" : "=f"(e) : "f"(x * -1.4426950408889634f));
    float r; asm("rcp.approx.f32 %0, %1;" : "=f"(r) : "f"(1.f + e));
    return r;
}
__device__ __forceinline__ float tanh_fast(float x) { return 2.f*sigf(2.f*x) - 1.f; }

// ---------------- bins helper ----------------
__device__ __forceinline__ int bin_of(float dx, float dy) {
    float dist = sqrtf(dx*dx + dy*dy);
    float dc = dist < 1e-10f ? 1e-10f : dist;
    float ct = acosf(fminf(fmaxf(dx/dc, -1.f), 1.f));
    float theta = (dy < -0.01f) ? (6.2831853071795864f - ct) : ct;
    const float R_STEP  = (float)(3.5/6.0);
    const float TH_STEP = (float)(6.283185307179586/6.0);
    int ub = (int)((dist - 0.5f)/R_STEP); ub = min(max(ub,0),5);
    int vb = (int)(theta/TH_STEP);        vb = min(max(vb,0),5);
    return ub*6 + vb;
}

// ---------------- conv1 + bins + init (merged, 7776 blocks x 256) ----------
__global__ void conv1x_kernel(const float* __restrict__ img,
                              const float* __restrict__ w,
                              const float* __restrict__ bias,
                              const float* __restrict__ y_path,
                              const float* __restrict__ hx) {
    __shared__ float sW[1600];
    __shared__ float sB[16];
    __shared__ float sP[8][NN][2];
    int blk = blockIdx.x, tid = threadIdx.x;
    if (blk < 6400) {
        // ---- conv1 ----
        for (int i = tid; i < 1600; i += 256) sW[i] = w[i];
        if (tid < 16) sB[tid] = bias[tid];
        __syncthreads();
        int idx = blk*256 + tid;
        int x = idx % HH2; int y = (idx/HH2) % HH2;
        int oc = (idx/(HH2*HH2)) % C1; int b = idx/(HH2*HH2*C1);
        float acc = sB[oc];
        for (int ic = 0; ic < 4; ic++)
            for (int ky = 0; ky < 5; ky++) {
                int iy = 2*y - 2 + ky;
                if (iy < 0 || iy >= 160) continue;
                const float* ip = img + ((b*4+ic)*160 + iy)*160;
                const float* wp = sW + (oc*4+ic)*25 + ky*5;
                #pragma unroll
                for (int kx = 0; kx < 5; kx++) {
                    int ix = 2*x - 2 + kx;
                    if (ix < 0 || ix >= 160) continue;
                    acc += ip[ix] * wp[kx];
                }
            }
        g_conv1[idx] = fmaxf(acc, 0.f);
    } else if (blk < 7680) {
        // ---- bins: 8 groups per block ----
        int g = tid >> 5, j = tid & 31;
        int grp = (blk - 6400)*8 + g;          // 10240 exact
        int b = grp % BB; int kt = grp / BB;
        int rowbase = kt*BN + b*NN;
        sP[g][j][0] = y_path[(rowbase+j)*2];
        sP[g][j][1] = y_path[(rowbase+j)*2+1];
        __syncwarp();
        float pjx = sP[g][j][0], pjy = sP[g][j][1];
        unsigned maskbits = 0;
        #pragma unroll
        for (int n2 = 0; n2 < NN; n2++) {
            float dx = sP[g][n2][0] - pjx;
            float dy = sP[g][n2][1] - pjy;
            float dist = sqrtf(dx*dx + dy*dy);
            if (n2 != j && dist >= 0.5f && dist <= 4.0f) maskbits |= 1u << n2;
        }
        size_t rowid = rowbase + j;
        int e = 0;
        unsigned m1 = maskbits;
        while (m1) {
            int n2 = __ffs(m1) - 1; m1 &= m1 - 1;
            int bn = bin_of(sP[g][n2][0]-pjx, sP[g][n2][1]-pjy);
            int cnt = 0;
            unsigned mq = maskbits;
            while (mq) {
                int q = __ffs(mq) - 1; mq &= mq - 1;
                cnt += (bin_of(sP[g][q][0]-pjx, sP[g][q][1]-pjy) == bn);
            }
            g_ent[rowid*32 + e] = make_float2(1.f/(float)cnt,
                                __int_as_float((n2*NBIN + bn)*48));
            e++;
        }
        g_cnt[rowid] = e;
    } else {
        // ---- init ----
        int idx = (blk - 7680)*256 + tid;      // 24576 exact
        g_h0[0][idx] = hx[idx];
        if (idx == 0) { g_bar_count = 0u; g_bar_flag = 0u; }
    }
}

// ---------------- conv2 (f32x2) ----------------
__global__ void conv2_kernel(const float* __restrict__ w2,
                             const float* __restrict__ b2) {
    __shared__ float sIn[6400];
    __shared__ __align__(16) float sW[3200];
    int blk = blockIdx.x;                       // 1600
    int ocg = blk % 4; int tile = (blk/4) % 25; int b = blk/100;
    int ty0 = (tile/5)*16, tx0 = (tile%5)*16;
    int tid = threadIdx.x;                      // 128
    for (int i = tid; i < 6400; i += 128) {
        int ic = i/400; int rem = i%400; int ly = rem/20, lx = rem%20;
        int iy = ty0 + ly - 2, ix = tx0 + lx - 2;
        sIn[i] = (iy>=0 && iy<HH2 && ix>=0 && ix<HH2)
                 ? g_conv1[((b*C1+ic)*HH2+iy)*HH2+ix] : 0.f;
    }
    for (int i = tid; i < 3200; i += 128) {
        int ic = i/200, rem = i%200, k2 = rem/8, ocl = rem%8;
        sW[i] = w2[(ocg*8+ocl)*400 + ic*25 + k2];
    }
    __syncthreads();
    int tx = tid % 16, tyh = tid / 16;
    ull a0[4], a1[4];
    #pragma unroll
    for (int o2 = 0; o2 < 4; o2++) {
        a0[o2] = pk2(b2[ocg*8+2*o2], b2[ocg*8+2*o2+1]);
        a1[o2] = a0[o2];
    }
    for (int ic = 0; ic < 16; ic++) {
        float in0[25], in1[25];
        const float* p0 = sIn + ic*400 + tyh*20 + tx;
        const float* p1 = p0 + 160;
        #pragma unroll
        for (int ky = 0; ky < 5; ky++)
            #pragma unroll
            for (int kx = 0; kx < 5; kx++) {
                in0[ky*5+kx] = p0[ky*20+kx];
                in1[ky*5+kx] = p1[ky*20+kx];
            }
        #pragma unroll
        for (int k2 = 0; k2 < 25; k2++) {
            ull i0 = pk2(in0[k2], in0[k2]);
            ull i1 = pk2(in1[k2], in1[k2]);
            const float* wb = &sW[(ic*25+k2)*8];
            #pragma unroll
            for (int o2 = 0; o2 < 4; o2++) {
                ull w = *(const ull*)(wb + 2*o2);
                fma2(a0[o2], i0, w); fma2(a1[o2], i1, w);
            }
        }
    }
    #pragma unroll
    for (int o2 = 0; o2 < 4; o2++) {
        float v0, v1, u0, u1;
        upk2(a0[o2], v0, v1); upk2(a1[o2], u0, u1);
        int oc = ocg*8 + 2*o2;
        float* d0 = &g_fmap[((b*HH2 + ty0+tyh  )*HH2 + tx0+tx)*C2 + oc];
        float* d1 = &g_fmap[((b*HH2 + ty0+tyh+8)*HH2 + tx0+tx)*C2 + oc];
        d0[0] = fmaxf(v0, 0.f); d0[1] = fmaxf(v1, 0.f);
        d1[0] = fmaxf(u0, 0.f); d1[1] = fmaxf(u1, 0.f);
    }
}

// ---------------- lhalf ----------------
__global__ void lhalf_kernel(const float* __restrict__ y_path,
                             const float* __restrict__ cur_loc,
                             const float* __restrict__ fvw,
                             const float* __restrict__ fvb) {
    int idx = blockIdx.x*256 + threadIdx.x;    // 7,864,320
    int cp = idx % 24; int row = idx / 24;
    int kt = row / BN, i2 = row % BN;
    int t = kt % TT; int b = i2 >> 5;
    float px = y_path[row*2], py = y_path[row*2+1];
    float2 out;
    if (cp < 16) {
        int u = 40 - (int)py; u = min(max(u,0), HH2-1);
        int v = (int)px;      v = min(max(v,0), HH2-1);
        out = *(const float2*)&g_fmap[((b*HH2+u)*HH2+v)*C2 + 2*cp];
    } else {
        int cc = 2*cp - 32;
        float pvx, pvy;
        if (t == 0) { pvx = cur_loc[i2*2]; pvy = cur_loc[i2*2+1]; }
        else { pvx = y_path[(row-BN)*2]; pvy = y_path[(row-BN)*2+1]; }
        float vx = (px-pvx)*10.f, vy = (py-pvy)*10.f;
        out.x = fvb[cc]   + vx*fvw[cc*2]   + vy*fvw[cc*2+1];
        out.y = fvb[cc+1] + vx*fvw[cc*2+2] + vy*fvw[cc*2+3];
    }
    *(float2*)&g_lhalf[(size_t)idx*2] = out;
}

// ---------------- grid barrier: release/acquire, no CCTL.IVALL ------------
__device__ __forceinline__ void gbar(unsigned target) {
    __syncthreads();
    if (threadIdx.x == 0) {
        unsigned old;
        asm volatile("atom.release.gpu.global.add.u32 %0, [%1], 1;"
                     : "=r"(old) : "l"(&g_bar_count) : "memory");
        if (old == NBLK - 1u) {
            g_bar_count = 0u;
            asm volatile("st.release.gpu.global.u32 [%0], %1;"
                         :: "l"(&g_bar_flag), "r"(target) : "memory");
        } else {
            unsigned v;
            do {
                asm volatile("ld.acquire.gpu.global.u32 %0, [%1];"
                             : "=r"(v) : "l"(&g_bar_flag) : "memory");
            } while (v < target);
        }
    }
    __syncthreads();
}

// ---------------- persistent fused scan ----------------
__global__ void __launch_bounds__(TSC, 1) scan_kernel(
        const float* __restrict__ hx,   const float* __restrict__ scfw,
        const float* __restrict__ whh,  const float* __restrict__ bhh,
        const float* __restrict__ wih,  const float* __restrict__ bih,
        const float* __restrict__ scfb, const float* __restrict__ scw) {
    extern __shared__ float sm[];
    float* sWT  = sm;              // 9216  Wscf og-slice (oo,hh,c)
    float* sWih = sm + 9216;       // 13920 (96 x 145)
    float* sWhh = sm + 23136;      // 6960  (48 x 145)
    float* sBi  = sm + 30096;      // 144
    float* sBh  = sm + 30240;      // 144
    float* sFb  = sm + 30384;      // 48
    float* sScw = sm + 30432;      // 48
    float* sHnT = sm + 30480;      // 1584 (48 x 33)
    float* sLT  = sm + 32064;      // 3168 (48 x 66) lhalf^T
    float* sRT  = sm + 35232;      // 3168 rhalf^T
    float* sBufA= sm + 38400;      // 3168 h^T ping
    float* sBufB= sm + 41568;      // 3168 h^T pong
    float2* sEnt = (float2*)(sm + 44736);  // 2048 fl
    int*   sCnt = (int*)(sm + 48832);      // 64
    float* sSc  = sm + 48896;      // 1536
    float* sScA = sm + 50432;      // 64 -> total 50496 fl

    int tid = threadIdx.x, blk = blockIdx.x;
    int bA = blk / 9, og = blk % 9;
    bool rowRole = (blk < 128);
    int r0 = blk * 64;
    int kq = r0 >> 9, i2b = r0 & 511;

    for (int i = tid; i < 9216; i += TSC) {
        int c = i % 48, rest = i / 48, hh = rest % 48, oo = rest / 48;
        sWT[oo*2304 + hh*48 + c] = scfw[c*1728 + (og*4+oo)*48 + hh];
    }
    for (int i = tid; i < 13824; i += TSC) {
        int c = i / 96, m = i % 96;
        sWih[m*145 + c] = wih[i];
    }
    for (int i = tid; i < 6912; i += TSC) {
        int c = i / 48, m = i % 48;
        sWhh[m*145 + c] = whh[i];
    }
    if (tid < 144) { sBi[tid] = bih[tid]; sBh[tid] = bhh[tid]; }
    if (tid < 48)  { sFb[tid] = scfb[tid]; sScw[tid] = scw[tid]; }
    if (tid < 64)  sScA[tid] = 0.f;
    float* pH = sBufA;
    float* pN = sBufB;
    if (rowRole)
        for (int i = tid; i < 3072; i += TSC) {
            int row = i / 48, c = i % 48;
            pH[c*66 + row] = hx[(i2b + row)*48 + c];
        }
    __syncthreads();

    unsigned bar = 0;
    for (int t = 0; t < TT; t++) {
        const float* hsrc = g_h0[t & 1] + bA*1536;
        for (int i = tid; i < 1536; i += TSC) {
            int n2 = i / 48, hh = i % 48;
            sHnT[hh*33 + n2] = __ldcg(hsrc + i);
        }
        int gb = 0;
        if (rowRole) {
            gb = (kq*TT + t)*BN + i2b;
            for (int i = tid; i < 3072; i += TSC) {
                int row = i / 48, c = i % 48;
                sLT[c*66 + row] = g_lhalf[(size_t)gb*48 + i];
            }
            if (tid < 64) {
                int cnt = g_cnt[gb + tid];
                sCnt[tid] = cnt;
                for (int e = 0; e < cnt; e++)
                    sEnt[tid*32 + e] = g_ent[(size_t)(gb + tid)*32 + e];
            }
        }
        __syncthreads();
        // ---- HW table slice ----
        for (int it = tid; it < 768; it += TSC) {
            int cg = it % 24, oo = (it/24) & 3, n2g = it / 96;
            float a0[4], a1[4];
            #pragma unroll
            for (int i = 0; i < 4; i++) { a0[i] = 0.f; a1[i] = 0.f; }
            const float* wt = sWT + oo*2304;
            for (int hh = 0; hh < 48; hh++) {
                float w0 = wt[hh*48 + cg], w1 = wt[hh*48 + cg + 24];
                #pragma unroll
                for (int i = 0; i < 4; i++) {
                    float hv = sHnT[hh*33 + n2g*4 + i];
                    a0[i] += hv*w0; a1[i] += hv*w1;
                }
            }
            #pragma unroll
            for (int i = 0; i < 4; i++) {
                int base = ((bA*NN + n2g*4+i)*NBIN + og*4 + oo)*48;
                g_HW[base + cg]      = a0[i];
                g_HW[base + cg + 24] = a1[i];
            }
        }
        gbar(++bar);
        if (rowRole) {
            // ---- gather ----
            for (int out = tid; out < 3072; out += TSC) {
                int lr = out / 48, c = out % 48;
                int cnt = sCnt[lr];
                float acc = sFb[c];
                const float* hwb = g_HW + ((i2b + lr) >> 5)*(NN*NBIN*48);
                for (int e = 0; e < cnt; e++) {
                    float2 en = sEnt[lr*32 + e];
                    acc += en.x * __ldcg(hwb + __float_as_int(en.y) + c);
                }
                sRT[c*66 + lr] = acc;
            }
            __syncthreads();
            // ---- fused f32x2 GEMM + GRU ----
            if (tid < 384) {
                int cg = tid % 24, rg = tid / 24, rl = rg*4;
                ull gr2[2][2], gz2[2][2], gnx2[2][2], gnh2[2][2];
                #pragma unroll
                for (int jj = 0; jj < 2; jj++) {
                    int c = cg + 24*jj;
                    ull t0;
                    t0 = pk2(sBi[c]+sBh[c],       sBi[c]+sBh[c]);
                    gr2[0][jj] = t0; gr2[1][jj] = t0;
                    t0 = pk2(sBi[48+c]+sBh[48+c], sBi[48+c]+sBh[48+c]);
                    gz2[0][jj] = t0; gz2[1][jj] = t0;
                    t0 = pk2(sBi[96+c], sBi[96+c]);
                    gnx2[0][jj] = t0; gnx2[1][jj] = t0;
                    t0 = pk2(sBh[96+c], sBh[96+c]);
                    gnh2[0][jj] = t0; gnh2[1][jj] = t0;
                }
                #define SEG(XS, WP, NACC)                                      \
                for (int m = 0; m < 48; m++) {                                 \
                    ull x0 = *(const ull*)&XS[m*66 + rl];                      \
                    ull x1 = *(const ull*)&XS[m*66 + rl + 2];                  \
                    const float* wp = WP + m*145;                              \
                    _Pragma("unroll")                                          \
                    for (int jj = 0; jj < 2; jj++) {                           \
                        int c = cg + 24*jj;                                    \
                        ull wr = pk2(wp[c], wp[c]);                            \
                        ull wz = pk2(wp[48+c], wp[48+c]);                      \
                        ull wn = pk2(wp[96+c], wp[96+c]);                      \
                        fma2(gr2[0][jj], x0, wr); fma2(gr2[1][jj], x1, wr);    \
                        fma2(gz2[0][jj], x0, wz); fma2(gz2[1][jj], x1, wz);    \
                        fma2(NACC[0][jj], x0, wn); fma2(NACC[1][jj], x1, wn);  \
                    }                                                          \
                }
                SEG(sLT, sWih, gnx2)
                SEG((sRT), (sWih + 48*145), gnx2)
                SEG(pH, sWhh, gnh2)
                #undef SEG
                float scacc[4] = {0.f, 0.f, 0.f, 0.f};
                #pragma unroll
                for (int p = 0; p < 2; p++) {
                    #pragma unroll
                    for (int jj = 0; jj < 2; jj++) {
                        int c = cg + 24*jj;
                        float grl, grh, gzl, gzh, gxl, gxh, ghl, ghh;
                        upk2(gr2[p][jj],  grl, grh);
                        upk2(gz2[p][jj],  gzl, gzh);
                        upk2(gnx2[p][jj], gxl, gxh);
                        upk2(gnh2[p][jj], ghl, ghh);
                        int rowl = rl + 2*p, rowh = rowl + 1;
                        float r0f = sigf(grl), z0f = sigf(gzl);
                        float n0f = tanh_fast(gxl + r0f*ghl);
                        float h0f = (1.f - z0f)*n0f + z0f*pH[c*66 + rowl];
                        pN[c*66 + rowl] = h0f;
                        scacc[2*p]   += h0f * sScw[c];
                        float r1f = sigf(grh), z1f = sigf(gzh);
                        float n1f = tanh_fast(gxh + r1f*ghh);
                        float h1f = (1.f - z1f)*n1f + z1f*pH[c*66 + rowh];
                        pN[c*66 + rowh] = h1f;
                        scacc[2*p+1] += h1f * sScw[c];
                    }
                }
                #pragma unroll
                for (int i = 0; i < 4; i++) sSc[(rl+i)*24 + cg] = scacc[i];
            }
            __syncthreads();
            if (tid < 64) {
                float s = 0.f;
                #pragma unroll
                for (int c = 0; c < 24; c++) s += sSc[tid*24 + c];
                sScA[tid] += s;
            }
            if (blk < 8) {
                float* dst = g_h0[1 - (t & 1)] + r0*48;
                for (int i = tid; i < 3072; i += TSC) {
                    int row = i / 48, c = i % 48;
                    dst[i] = pN[c*66 + row];
                }
            }
        }
        // swap ping-pong (uniform across threads)
        { float* tmp = pH; pH = pN; pN = tmp; }
        gbar(++bar);
    }
    if (rowRole) {
        for (int i = tid; i < 3072; i += TSC) {
            int row = i / 48, c = i % 48;
            g_hfin[(size_t)r0*48 + i] = pH[c*66 + row];
        }
        if (tid < 64) g_score[r0 + tid] = sScA[tid];
    }
}

// ---------------- final ----------------
__global__ void final_kernel(const float* __restrict__ dyw,
                             const float* __restrict__ dyb,
                             const float* __restrict__ scb,
                             float* __restrict__ out) {
    int idx = blockIdx.x*256 + threadIdx.x;    // 663552
    if (idx < KBN*80) {
        int row = idx / 80, c = idx % 80;
        float acc = dyb[c];
        const float* hr = g_hfin + row*48;
        const float* w  = dyw + c*48;
        #pragma unroll 8
        for (int hh = 0; hh < 48; hh++) acc += hr[hh]*w[hh];
        int k = row >> 9, i2 = row & 511;
        int d = c / 40, tt = c % 40;
        out[((k*TT + tt)*BN + i2)*2 + d] = acc;
    } else {
        int row = idx - KBN*80;
        out[KBN*80 + row] = g_score[row] + 40.f*scb[0];
    }
}

// ---------------- launcher ----------------
extern "C" void kernel_launch(void* const* d_in, const int* in_sizes, int n_in,
                              void* d_out, int out_size) {
    const float* hx      = (const float*)d_in[0];
    const float* cur_loc = (const float*)d_in[1];
    const float* y_path  = (const float*)d_in[2];
    const float* image   = (const float*)d_in[3];
    const float* c1w     = (const float*)d_in[4];
    const float* c1b     = (const float*)d_in[5];
    const float* c2w     = (const float*)d_in[6];
    const float* c2b     = (const float*)d_in[7];
    const float* fvw     = (const float*)d_in[8];
    const float* fvb     = (const float*)d_in[9];
    const float* scfw    = (const float*)d_in[10];
    const float* scfb    = (const float*)d_in[11];
    const float* wih     = (const float*)d_in[12];
    const float* whh     = (const float*)d_in[13];
    const float* bih     = (const float*)d_in[14];
    const float* bhh     = (const float*)d_in[15];
    const float* dyw     = (const float*)d_in[16];
    const float* dyb     = (const float*)d_in[17];
    const float* scw     = (const float*)d_in[18];
    const float* scb     = (const float*)d_in[19];

    const int SMEM_SCAN = 50496 * 4;           // 201984 B
    cudaFuncSetAttribute(scan_kernel,
                         cudaFuncAttributeMaxDynamicSharedMemorySize, SMEM_SCAN);

    conv1x_kernel<<<7776, 256>>>(image, c1w, c1b, y_path, hx);
    conv2_kernel <<<1600, 128>>>(c2w, c2b);
    lhalf_kernel <<<30720,256>>>(y_path, cur_loc, fvw, fvb);
    scan_kernel  <<<NBLK, TSC, SMEM_SCAN>>>(hx, scfw, whh, bhh, wih, bih, scfb, scw);
    final_kernel <<<2592, 256>>>(dyw, dyb, scb, (float*)d_out);
}

// round 12
// speedup vs baseline: 1.4516x; 1.0458x over previous
#include <cuda_runtime.h>
#include <math.h>

#define KK 16
#define TT 40
#define BB 16
#define NN 32
#define BN 512
#define KBN 8192
#define HH2 80
#define C1 16
#define C2 32
#define NBIN 36
#define NBLK 144
#define TSC 512

typedef unsigned long long ull;

__device__ float g_conv1[BB*C1*HH2*HH2];
__device__ float g_fmap [BB*HH2*HH2*C2];
__device__ float g_lhalf[KK*TT*BN*48];
__device__ int   g_cnt[KK*TT*BN];
__device__ float2 g_ent[(size_t)KK*TT*BN*32];
__device__ float g_HW [BB*NN*NBIN*48];
__device__ float g_h0 [2][BN*48];
__device__ float g_hfin[KBN*48];
__device__ float g_score[KBN];
__device__ unsigned g_bar_count;
__device__ unsigned g_bar_flag;

// ---- f32x2 / fast-math helpers ----
__device__ __forceinline__ ull pk2(float lo, float hi) {
    ull r; asm("mov.b64 %0, {%1,%2};" : "=l"(r) : "f"(lo), "f"(hi)); return r;
}
__device__ __forceinline__ void upk2(ull v, float& lo, float& hi) {
    asm("mov.b64 {%0,%1}, %2;" : "=f"(lo), "=f"(hi) : "l"(v));
}
__device__ __forceinline__ void fma2(ull& a, ull x, ull y) {
    asm("fma.rn.f32x2 %0, %1, %2, %0;" : "+l"(a) : "l"(x), "l"(y));
}
__device__ __forceinline__ float sigf(float x) {
    float e; asm("ex2.approx.f32 %0, %1;" : "=f"(e) : "f"(x * -1.4426950408889634f));
    float r; asm("rcp.approx.f32 %0, %1;" : "=f"(r) : "f"(1.f + e));
    return r;
}
__device__ __forceinline__ float tanh_fast(float x) { return 2.f*sigf(2.f*x) - 1.f; }

// ---------------- bins helper ----------------
__device__ __forceinline__ int bin_of(float dx, float dy) {
    float dist = sqrtf(dx*dx + dy*dy);
    float dc = dist < 1e-10f ? 1e-10f : dist;
    float ct = acosf(fminf(fmaxf(dx/dc, -1.f), 1.f));
    float theta = (dy < -0.01f) ? (6.2831853071795864f - ct) : ct;
    const float R_STEP  = (float)(3.5/6.0);
    const float TH_STEP = (float)(6.283185307179586/6.0);
    int ub = (int)((dist - 0.5f)/R_STEP); ub = min(max(ub,0),5);
    int vb = (int)(theta/TH_STEP);        vb = min(max(vb,0),5);
    return ub*6 + vb;
}

// ---------------- conv1 + bins + init (merged) ----------------
__global__ void conv1x_kernel(const float* __restrict__ img,
                              const float* __restrict__ w,
                              const float* __restrict__ bias,
                              const float* __restrict__ y_path,
                              const float* __restrict__ hx) {
    __shared__ float sW[1600];
    __shared__ float sB[16];
    __shared__ float sP[8][NN][2];
    int blk = blockIdx.x, tid = threadIdx.x;
    if (blk < 6400) {
        for (int i = tid; i < 1600; i += 256) sW[i] = w[i];
        if (tid < 16) sB[tid] = bias[tid];
        __syncthreads();
        int idx = blk*256 + tid;
        int x = idx % HH2; int y = (idx/HH2) % HH2;
        int oc = (idx/(HH2*HH2)) % C1; int b = idx/(HH2*HH2*C1);
        float acc = sB[oc];
        for (int ic = 0; ic < 4; ic++)
            for (int ky = 0; ky < 5; ky++) {
                int iy = 2*y - 2 + ky;
                if (iy < 0 || iy >= 160) continue;
                const float* ip = img + ((b*4+ic)*160 + iy)*160;
                const float* wp = sW + (oc*4+ic)*25 + ky*5;
                #pragma unroll
                for (int kx = 0; kx < 5; kx++) {
                    int ix = 2*x - 2 + kx;
                    if (ix < 0 || ix >= 160) continue;
                    acc += ip[ix] * wp[kx];
                }
            }
        g_conv1[idx] = fmaxf(acc, 0.f);
    } else if (blk < 7680) {
        int g = tid >> 5, j = tid & 31;
        int grp = (blk - 6400)*8 + g;          // 10240 exact
        int b = grp % BB; int kt = grp / BB;
        int rowbase = kt*BN + b*NN;
        sP[g][j][0] = y_path[(rowbase+j)*2];
        sP[g][j][1] = y_path[(rowbase+j)*2+1];
        __syncwarp();
        float pjx = sP[g][j][0], pjy = sP[g][j][1];
        unsigned maskbits = 0;
        #pragma unroll
        for (int n2 = 0; n2 < NN; n2++) {
            float dx = sP[g][n2][0] - pjx;
            float dy = sP[g][n2][1] - pjy;
            float dist = sqrtf(dx*dx + dy*dy);
            if (n2 != j && dist >= 0.5f && dist <= 4.0f) maskbits |= 1u << n2;
        }
        size_t rowid = rowbase + j;
        int e = 0;
        unsigned m1 = maskbits;
        while (m1) {
            int n2 = __ffs(m1) - 1; m1 &= m1 - 1;
            int bn = bin_of(sP[g][n2][0]-pjx, sP[g][n2][1]-pjy);
            int cnt = 0;
            unsigned mq = maskbits;
            while (mq) {
                int q = __ffs(mq) - 1; mq &= mq - 1;
                cnt += (bin_of(sP[g][q][0]-pjx, sP[g][q][1]-pjy) == bn);
            }
            g_ent[rowid*32 + e] = make_float2(1.f/(float)cnt,
                                __int_as_float((n2*NBIN + bn)*48));
            e++;
        }
        g_cnt[rowid] = e;
    } else {
        int idx = (blk - 7680)*256 + tid;      // 24576 exact
        g_h0[0][idx] = hx[idx];
        if (idx == 0) { g_bar_count = 0u; g_bar_flag = 0u; }
    }
}

// ---------------- conv2 (f32x2) ----------------
__global__ void conv2_kernel(const float* __restrict__ w2,
                             const float* __restrict__ b2) {
    __shared__ float sIn[6400];
    __shared__ __align__(16) float sW[3200];
    int blk = blockIdx.x;                       // 1600
    int ocg = blk % 4; int tile = (blk/4) % 25; int b = blk/100;
    int ty0 = (tile/5)*16, tx0 = (tile%5)*16;
    int tid = threadIdx.x;                      // 128
    for (int i = tid; i < 6400; i += 128) {
        int ic = i/400; int rem = i%400; int ly = rem/20, lx = rem%20;
        int iy = ty0 + ly - 2, ix = tx0 + lx - 2;
        sIn[i] = (iy>=0 && iy<HH2 && ix>=0 && ix<HH2)
                 ? g_conv1[((b*C1+ic)*HH2+iy)*HH2+ix] : 0.f;
    }
    for (int i = tid; i < 3200; i += 128) {
        int ic = i/200, rem = i%200, k2 = rem/8, ocl = rem%8;
        sW[i] = w2[(ocg*8+ocl)*400 + ic*25 + k2];
    }
    __syncthreads();
    int tx = tid % 16, tyh = tid / 16;
    ull a0[4], a1[4];
    #pragma unroll
    for (int o2 = 0; o2 < 4; o2++) {
        a0[o2] = pk2(b2[ocg*8+2*o2], b2[ocg*8+2*o2+1]);
        a1[o2] = a0[o2];
    }
    for (int ic = 0; ic < 16; ic++) {
        float in0[25], in1[25];
        const float* p0 = sIn + ic*400 + tyh*20 + tx;
        const float* p1 = p0 + 160;
        #pragma unroll
        for (int ky = 0; ky < 5; ky++)
            #pragma unroll
            for (int kx = 0; kx < 5; kx++) {
                in0[ky*5+kx] = p0[ky*20+kx];
                in1[ky*5+kx] = p1[ky*20+kx];
            }
        #pragma unroll
        for (int k2 = 0; k2 < 25; k2++) {
            ull i0 = pk2(in0[k2], in0[k2]);
            ull i1 = pk2(in1[k2], in1[k2]);
            const float* wb = &sW[(ic*25+k2)*8];
            #pragma unroll
            for (int o2 = 0; o2 < 4; o2++) {
                ull w = *(const ull*)(wb + 2*o2);
                fma2(a0[o2], i0, w); fma2(a1[o2], i1, w);
            }
        }
    }
    #pragma unroll
    for (int o2 = 0; o2 < 4; o2++) {
        float v0, v1, u0, u1;
        upk2(a0[o2], v0, v1); upk2(a1[o2], u0, u1);
        int oc = ocg*8 + 2*o2;
        float* d0 = &g_fmap[((b*HH2 + ty0+tyh  )*HH2 + tx0+tx)*C2 + oc];
        float* d1 = &g_fmap[((b*HH2 + ty0+tyh+8)*HH2 + tx0+tx)*C2 + oc];
        d0[0] = fmaxf(v0, 0.f); d0[1] = fmaxf(v1, 0.f);
        d1[0] = fmaxf(u0, 0.f); d1[1] = fmaxf(u1, 0.f);
    }
}

// ---------------- lhalf ----------------
__global__ void lhalf_kernel(const float* __restrict__ y_path,
                             const float* __restrict__ cur_loc,
                             const float* __restrict__ fvw,
                             const float* __restrict__ fvb) {
    int idx = blockIdx.x*256 + threadIdx.x;    // 7,864,320
    int cp = idx % 24; int row = idx / 24;
    int kt = row / BN, i2 = row % BN;
    int t = kt % TT; int b = i2 >> 5;
    float px = y_path[row*2], py = y_path[row*2+1];
    float2 out;
    if (cp < 16) {
        int u = 40 - (int)py; u = min(max(u,0), HH2-1);
        int v = (int)px;      v = min(max(v,0), HH2-1);
        out = *(const float2*)&g_fmap[((b*HH2+u)*HH2+v)*C2 + 2*cp];
    } else {
        int cc = 2*cp - 32;
        float pvx, pvy;
        if (t == 0) { pvx = cur_loc[i2*2]; pvy = cur_loc[i2*2+1]; }
        else { pvx = y_path[(row-BN)*2]; pvy = y_path[(row-BN)*2+1]; }
        float vx = (px-pvx)*10.f, vy = (py-pvy)*10.f;
        out.x = fvb[cc]   + vx*fvw[cc*2]   + vy*fvw[cc*2+1];
        out.y = fvb[cc+1] + vx*fvw[cc*2+2] + vy*fvw[cc*2+3];
    }
    *(float2*)&g_lhalf[(size_t)idx*2] = out;
}

// ---------------- grid barrier: release/acquire + nanosleep ---------------
__device__ __forceinline__ void gbar(unsigned target) {
    __syncthreads();
    if (threadIdx.x == 0) {
        unsigned old;
        asm volatile("atom.release.gpu.global.add.u32 %0, [%1], 1;"
                     : "=r"(old) : "l"(&g_bar_count) : "memory");
        if (old == NBLK - 1u) {
            g_bar_count = 0u;
            asm volatile("st.release.gpu.global.u32 [%0], %1;"
                         :: "l"(&g_bar_flag), "r"(target) : "memory");
        } else {
            unsigned v;
            do {
                __nanosleep(20);
                asm volatile("ld.acquire.gpu.global.u32 %0, [%1];"
                             : "=r"(v) : "l"(&g_bar_flag) : "memory");
            } while (v < target);
        }
    }
    __syncthreads();
}

// ---------------- persistent fused scan ----------------
__global__ void __launch_bounds__(TSC, 1) scan_kernel(
        const float* __restrict__ hx,   const float* __restrict__ scfw,
        const float* __restrict__ whh,  const float* __restrict__ bhh,
        const float* __restrict__ wih,  const float* __restrict__ bih,
        const float* __restrict__ scfb, const float* __restrict__ scw) {
    extern __shared__ float sm[];
    float* sWT  = sm;              // 9216  Wscf og-slice (oo,hh,c)
    float* sWih = sm + 9216;       // 13920 (96 x 145)
    float* sWhh = sm + 23136;      // 6960  (48 x 145)
    float* sBi  = sm + 30096;      // 144
    float* sBh  = sm + 30240;      // 144
    float* sFb  = sm + 30384;      // 48
    float* sScw = sm + 30432;      // 48
    float* sHnT = sm + 30480;      // 1584 (48 x 33)
    float* sLT  = sm + 32064;      // 3168 (48 x 66) lhalf^T
    float* sRT  = sm + 35232;      // 3168 rhalf^T
    float* sBufA= sm + 38400;      // 3168 h^T ping
    float* sBufB= sm + 41568;      // 3168 h^T pong
    float2* sEnt = (float2*)(sm + 44736);  // 4096 fl (64 x 32 float2)
    int*   sCnt = (int*)(sm + 48832);      // 64
    float* sSc  = sm + 48896;      // 1536
    float* sScA = sm + 50432;      // 64 -> total 50496 fl

    int tid = threadIdx.x, blk = blockIdx.x;
    int bA = blk / 9, og = blk % 9;
    bool rowRole = (blk < 128);
    int r0 = blk * 64;
    int kq = r0 >> 9, i2b = r0 & 511;

    for (int i = tid; i < 9216; i += TSC) {
        int c = i % 48, rest = i / 48, hh = rest % 48, oo = rest / 48;
        sWT[oo*2304 + hh*48 + c] = scfw[c*1728 + (og*4+oo)*48 + hh];
    }
    for (int i = tid; i < 13824; i += TSC) {
        int c = i / 96, m = i % 96;
        sWih[m*145 + c] = wih[i];
    }
    for (int i = tid; i < 6912; i += TSC) {
        int c = i / 48, m = i % 48;
        sWhh[m*145 + c] = whh[i];
    }
    if (tid < 144) { sBi[tid] = bih[tid]; sBh[tid] = bhh[tid]; }
    if (tid < 48)  { sFb[tid] = scfb[tid]; sScw[tid] = scw[tid]; }
    if (tid < 64)  sScA[tid] = 0.f;
    float* pH = sBufA;
    float* pN = sBufB;
    if (rowRole)
        for (int i = tid; i < 3072; i += TSC) {
            int row = i / 48, c = i % 48;
            pH[c*66 + row] = hx[(i2b + row)*48 + c];
        }
    __syncthreads();

    unsigned bar = 0;
    for (int t = 0; t < TT; t++) {
        // ---- h0 slice (needed for HW now) ----
        const float* hsrc = g_h0[t & 1] + bA*1536;
        for (int i = tid; i < 1536; i += TSC) {
            int n2 = i / 48, hh = i % 48;
            sHnT[hh*33 + n2] = __ldcg(hsrc + i);
        }
        __syncthreads();
        // ---- issue static loads for this step; they land during HW compute
        int gb = 0;
        if (rowRole) {
            gb = (kq*TT + t)*BN + i2b;
            for (int i = tid; i < 3072; i += TSC) {
                int row = i / 48, c = i % 48;
                sLT[c*66 + row] = g_lhalf[(size_t)gb*48 + i];
            }
            if (tid < 64) {
                int cnt = g_cnt[gb + tid];
                sCnt[tid] = cnt;
                for (int e = 0; e < cnt; e++)
                    sEnt[tid*32 + e] = g_ent[(size_t)(gb + tid)*32 + e];
            }
        }
        // ---- HW table slice ----
        for (int it = tid; it < 768; it += TSC) {
            int cg = it % 24, oo = (it/24) & 3, n2g = it / 96;
            float a0[4], a1[4];
            #pragma unroll
            for (int i = 0; i < 4; i++) { a0[i] = 0.f; a1[i] = 0.f; }
            const float* wt = sWT + oo*2304;
            for (int hh = 0; hh < 48; hh++) {
                float w0 = wt[hh*48 + cg], w1 = wt[hh*48 + cg + 24];
                #pragma unroll
                for (int i = 0; i < 4; i++) {
                    float hv = sHnT[hh*33 + n2g*4 + i];
                    a0[i] += hv*w0; a1[i] += hv*w1;
                }
            }
            #pragma unroll
            for (int i = 0; i < 4; i++) {
                int base = ((bA*NN + n2g*4+i)*NBIN + og*4 + oo)*48;
                g_HW[base + cg]      = a0[i];
                g_HW[base + cg + 24] = a1[i];
            }
        }
        gbar(++bar);
        if (rowRole) {
            // ---- gather ----
            for (int out = tid; out < 3072; out += TSC) {
                int lr = out / 48, c = out % 48;
                int cnt = sCnt[lr];
                float acc = sFb[c];
                const float* hwb = g_HW + ((i2b + lr) >> 5)*(NN*NBIN*48);
                for (int e = 0; e < cnt; e++) {
                    float2 en = sEnt[lr*32 + e];
                    acc += en.x * __ldcg(hwb + __float_as_int(en.y) + c);
                }
                sRT[c*66 + lr] = acc;
            }
            __syncthreads();
            // ---- fused f32x2 GEMM (8-row x 2-col tiles, 192 threads) ----
            if (tid < 192) {
                int cg = tid % 24, rg = tid / 24, rl = rg*8;
                ull gr2[4][2], gz2[4][2], gnx2[4][2], gnh2[4][2];
                #pragma unroll
                for (int jj = 0; jj < 2; jj++) {
                    int c = cg + 24*jj;
                    ull t0;
                    t0 = pk2(sBi[c]+sBh[c], sBi[c]+sBh[c]);
                    #pragma unroll
                    for (int p = 0; p < 4; p++) gr2[p][jj] = t0;
                    t0 = pk2(sBi[48+c]+sBh[48+c], sBi[48+c]+sBh[48+c]);
                    #pragma unroll
                    for (int p = 0; p < 4; p++) gz2[p][jj] = t0;
                    t0 = pk2(sBi[96+c], sBi[96+c]);
                    #pragma unroll
                    for (int p = 0; p < 4; p++) gnx2[p][jj] = t0;
                    t0 = pk2(sBh[96+c], sBh[96+c]);
                    #pragma unroll
                    for (int p = 0; p < 4; p++) gnh2[p][jj] = t0;
                }
                #define SEG(XS, WP, NACC)                                      \
                for (int m = 0; m < 48; m++) {                                 \
                    ull xv[4];                                                 \
                    _Pragma("unroll")                                          \
                    for (int p = 0; p < 4; p++)                                \
                        xv[p] = *(const ull*)&XS[m*66 + rl + 2*p];             \
                    const float* wp = WP + m*145;                              \
                    _Pragma("unroll")                                          \
                    for (int jj = 0; jj < 2; jj++) {                           \
                        int c = cg + 24*jj;                                    \
                        ull wr = pk2(wp[c], wp[c]);                            \
                        ull wz = pk2(wp[48+c], wp[48+c]);                      \
                        ull wn = pk2(wp[96+c], wp[96+c]);                      \
                        _Pragma("unroll")                                      \
                        for (int p = 0; p < 4; p++) {                          \
                            fma2(gr2[p][jj], xv[p], wr);                       \
                            fma2(gz2[p][jj], xv[p], wz);                       \
                            fma2(NACC[p][jj], xv[p], wn);                      \
                        }                                                      \
                    }                                                          \
                }
                SEG(sLT, sWih, gnx2)
                SEG((sRT), (sWih + 48*145), gnx2)
                SEG(pH, sWhh, gnh2)
                #undef SEG
                #pragma unroll
                for (int p = 0; p < 4; p++) {
                    int rowl = rl + 2*p, rowh = rowl + 1;
                    float scl = 0.f, sch = 0.f;
                    #pragma unroll
                    for (int jj = 0; jj < 2; jj++) {
                        int c = cg + 24*jj;
                        float grl, grh, gzl, gzh, gxl, gxh, ghl, ghh;
                        upk2(gr2[p][jj],  grl, grh);
                        upk2(gz2[p][jj],  gzl, gzh);
                        upk2(gnx2[p][jj], gxl, gxh);
                        upk2(gnh2[p][jj], ghl, ghh);
                        float r0f = sigf(grl), z0f = sigf(gzl);
                        float n0f = tanh_fast(gxl + r0f*ghl);
                        float h0f = (1.f - z0f)*n0f + z0f*pH[c*66 + rowl];
                        pN[c*66 + rowl] = h0f;
                        scl += h0f * sScw[c];
                        float r1f = sigf(grh), z1f = sigf(gzh);
                        float n1f = tanh_fast(gxh + r1f*ghh);
                        float h1f = (1.f - z1f)*n1f + z1f*pH[c*66 + rowh];
                        pN[c*66 + rowh] = h1f;
                        sch += h1f * sScw[c];
                    }
                    sSc[rowl*24 + cg] = scl;
                    sSc[rowh*24 + cg] = sch;
                }
            }
            __syncthreads();
            if (tid < 64) {
                float s = 0.f;
                #pragma unroll
                for (int c = 0; c < 24; c++) s += sSc[tid*24 + c];
                sScA[tid] += s;
            }
            if (blk < 8) {
                float* dst = g_h0[1 - (t & 1)] + r0*48;
                for (int i = tid; i < 3072; i += TSC) {
                    int row = i / 48, c = i % 48;
                    dst[i] = pN[c*66 + row];
                }
            }
        }
        { float* tmp = pH; pH = pN; pN = tmp; }
        gbar(++bar);
    }
    if (rowRole) {
        for (int i = tid; i < 3072; i += TSC) {
            int row = i / 48, c = i % 48;
            g_hfin[(size_t)r0*48 + i] = pH[c*66 + row];
        }
        if (tid < 64) g_score[r0 + tid] = sScA[tid];
    }
}

// ---------------- final ----------------
__global__ void final_kernel(const float* __restrict__ dyw,
                             const float* __restrict__ dyb,
                             const float* __restrict__ scb,
                             float* __restrict__ out) {
    int idx = blockIdx.x*256 + threadIdx.x;    // 663552
    if (idx < KBN*80) {
        int row = idx / 80, c = idx % 80;
        float acc = dyb[c];
        const float* hr = g_hfin + row*48;
        const float* w  = dyw + c*48;
        #pragma unroll 8
        for (int hh = 0; hh < 48; hh++) acc += hr[hh]*w[hh];
        int k = row >> 9, i2 = row & 511;
        int d = c / 40, tt = c % 40;
        out[((k*TT + tt)*BN + i2)*2 + d] = acc;
    } else {
        int row = idx - KBN*80;
        out[KBN*80 + row] = g_score[row] + 40.f*scb[0];
    }
}

// ---------------- launcher ----------------
extern "C" void kernel_launch(void* const* d_in, const int* in_sizes, int n_in,
                              void* d_out, int out_size) {
    const float* hx      = (const float*)d_in[0];
    const float* cur_loc = (const float*)d_in[1];
    const float* y_path  = (const float*)d_in[2];
    const float* image   = (const float*)d_in[3];
    const float* c1w     = (const float*)d_in[4];
    const float* c1b     = (const float*)d_in[5];
    const float* c2w     = (const float*)d_in[6];
    const float* c2b     = (const float*)d_in[7];
    const float* fvw     = (const float*)d_in[8];
    const float* fvb     = (const float*)d_in[9];
    const float* scfw    = (const float*)d_in[10];
    const float* scfb    = (const float*)d_in[11];
    const float* wih     = (const float*)d_in[12];
    const float* whh     = (const float*)d_in[13];
    const float* bih     = (const float*)d_in[14];
    const float* bhh     = (const float*)d_in[15];
    const float* dyw     = (const float*)d_in[16];
    const float* dyb     = (const float*)d_in[17];
    const float* scw     = (const float*)d_in[18];
    const float* scb     = (const float*)d_in[19];

    const int SMEM_SCAN = 50496 * 4;           // 201984 B
    cudaFuncSetAttribute(scan_kernel,
                         cudaFuncAttributeMaxDynamicSharedMemorySize, SMEM_SCAN);

    conv1x_kernel<<<7776, 256>>>(image, c1w, c1b, y_path, hx);
    conv2_kernel <<<1600, 128>>>(c2w, c2b);
    lhalf_kernel <<<30720,256>>>(y_path, cur_loc, fvw, fvb);
    scan_kernel  <<<NBLK, TSC, SMEM_SCAN>>>(hx, scfw, whh, bhh, wih, bih, scfb, scw);
    final_kernel <<<2592, 256>>>(dyw, dyb, scb, (float*)d_out);
}